// round 1
// baseline (speedup 1.0000x reference)
#include <cuda_runtime.h>
#include <cstddef>

#define NS 2000
#define NG 10000
#define NSOAP 6144

struct Ptrs { const float* v[6]; const float* g[6]; };

__constant__ float FAC[6] = {
    1.0f,
    0.5773502691896258f,   // 1/sqrt(3)
    0.4472135954999579f,   // 1/sqrt(5)
    0.3779644730092272f,   // 1/sqrt(7)
    0.3333333333333333f,   // 1/sqrt(9)
    0.30151134457776363f   // 1/sqrt(11)
};

// smem offset for l-block: sum_{l'<l} (2l'+1)*32 = 32*l*l
__device__ __forceinline__ int loff(int l) { return 32 * l * l; }

// ---------------------------------------------------------------------------
// values: out[i, l_block, a, b] = fac_l * sum_m v[i,m,a] * v[i,m,b]
// 1 block per i; 6 warps, warp w handles l=w; lane computes 8x4 tile.
// ---------------------------------------------------------------------------
__global__ void __launch_bounds__(192) values_kernel(Ptrs p, float* __restrict__ out) {
    __shared__ __align__(16) float sv[1152];
    const int i = blockIdx.x;
    const int tid = threadIdx.x;

    // cooperative load of all l-blocks of v[i]
#pragma unroll
    for (int l = 0; l < 6; ++l) {
        const int cnt4 = (2 * l + 1) * 8;  // float4 count
        const float4* src = (const float4*)(p.v[l] + (size_t)i * (2 * l + 1) * 32);
        float4* dst = (float4*)(sv + loff(l));
        for (int j = tid; j < cnt4; j += 192) dst[j] = src[j];
    }
    __syncthreads();

    const int l = tid >> 5;       // warp id == l
    const int lane = tid & 31;
    const int a0 = (lane >> 3) * 8;   // 4 row-groups of 8
    const int b0 = (lane & 7) * 4;    // 8 col-groups of 4
    const float* base = sv + loff(l);
    const int M = 2 * l + 1;

    float acc[8][4];
#pragma unroll
    for (int r = 0; r < 8; ++r)
#pragma unroll
        for (int c = 0; c < 4; ++c) acc[r][c] = 0.0f;

    for (int m = 0; m < M; ++m) {
        const float* row = base + m * 32;
        float4 a0v = *(const float4*)(row + a0);
        float4 a1v = *(const float4*)(row + a0 + 4);
        float4 bv  = *(const float4*)(row + b0);
        float av[8] = {a0v.x, a0v.y, a0v.z, a0v.w, a1v.x, a1v.y, a1v.z, a1v.w};
        float bb[4] = {bv.x, bv.y, bv.z, bv.w};
#pragma unroll
        for (int r = 0; r < 8; ++r)
#pragma unroll
            for (int c = 0; c < 4; ++c) acc[r][c] += av[r] * bb[c];
    }

    const float fac = FAC[l];
    float* o = out + (size_t)i * NSOAP + l * 1024 + a0 * 32 + b0;
#pragma unroll
    for (int r = 0; r < 8; ++r) {
        float4 s = make_float4(fac * acc[r][0], fac * acc[r][1],
                               fac * acc[r][2], fac * acc[r][3]);
        __stcs((float4*)(o + r * 32), s);
    }
}

// ---------------------------------------------------------------------------
// grads: out[i, x, l_block, a, b] = sum_m ( g[i,x,m,a]*vg[m,b] + vg[m,a]*g[i,x,m,b] )
// with vg = fac_l * v[idx[i]].  1 block per (x, i); same warp/tile layout.
// ---------------------------------------------------------------------------
__global__ void __launch_bounds__(192) grads_kernel(Ptrs p,
                                                    const int* __restrict__ gidx,
                                                    float* __restrict__ out) {
    __shared__ __align__(16) float sg[1152];
    __shared__ __align__(16) float svg[1152];
    const int x = blockIdx.x;   // 0..2
    const int i = blockIdx.y;   // 0..NG-1
    const int tid = threadIdx.x;
    const int s = gidx[i];

#pragma unroll
    for (int l = 0; l < 6; ++l) {
        const int cnt4 = (2 * l + 1) * 8;
        const float4* gs = (const float4*)(p.g[l] + ((size_t)(i * 3 + x)) * (2 * l + 1) * 32);
        const float4* vs = (const float4*)(p.v[l] + (size_t)s * (2 * l + 1) * 32);
        const float fac = FAC[l];
        float4* dg = (float4*)(sg + loff(l));
        float4* dv = (float4*)(svg + loff(l));
        for (int j = tid; j < cnt4; j += 192) {
            dg[j] = __ldcs(gs + j);           // read-once: stream past L2
            float4 t = vs[j];                  // reused across blocks: keep in L2
            dv[j] = make_float4(fac * t.x, fac * t.y, fac * t.z, fac * t.w);
        }
    }
    __syncthreads();

    const int l = tid >> 5;
    const int lane = tid & 31;
    const int a0 = (lane >> 3) * 8;
    const int b0 = (lane & 7) * 4;
    const float* gb = sg + loff(l);
    const float* vb = svg + loff(l);
    const int M = 2 * l + 1;

    float acc[8][4];
#pragma unroll
    for (int r = 0; r < 8; ++r)
#pragma unroll
        for (int c = 0; c < 4; ++c) acc[r][c] = 0.0f;

    for (int m = 0; m < M; ++m) {
        const float* rg = gb + m * 32;
        const float* rv = vb + m * 32;
        float4 ga0 = *(const float4*)(rg + a0);
        float4 ga1 = *(const float4*)(rg + a0 + 4);
        float4 va0 = *(const float4*)(rv + a0);
        float4 va1 = *(const float4*)(rv + a0 + 4);
        float4 gb4 = *(const float4*)(rg + b0);
        float4 vb4 = *(const float4*)(rv + b0);
        float ga[8] = {ga0.x, ga0.y, ga0.z, ga0.w, ga1.x, ga1.y, ga1.z, ga1.w};
        float va[8] = {va0.x, va0.y, va0.z, va0.w, va1.x, va1.y, va1.z, va1.w};
        float gc[4] = {gb4.x, gb4.y, gb4.z, gb4.w};
        float vc[4] = {vb4.x, vb4.y, vb4.z, vb4.w};
#pragma unroll
        for (int r = 0; r < 8; ++r)
#pragma unroll
            for (int c = 0; c < 4; ++c)
                acc[r][c] += ga[r] * vc[c] + va[r] * gc[c];
    }

    float* o = out + ((size_t)(i * 3 + x)) * NSOAP + l * 1024 + a0 * 32 + b0;
#pragma unroll
    for (int r = 0; r < 8; ++r) {
        float4 sv4 = make_float4(acc[r][0], acc[r][1], acc[r][2], acc[r][3]);
        __stcs((float4*)(o + r * 32), sv4);
    }
}

// ---------------------------------------------------------------------------
extern "C" void kernel_launch(void* const* d_in, const int* in_sizes, int n_in,
                              void* d_out, int out_size) {
    Ptrs p;
    const int* gidx = nullptr;
    // classify inputs by element count (all counts are distinct)
    for (int k = 0; k < n_in; ++k) {
        const int sz = in_sizes[k];
        if (sz == NG) { gidx = (const int*)d_in[k]; continue; }
        for (int l = 0; l < 6; ++l) {
            const int M = 2 * l + 1;
            if (sz == NS * M * 32)          p.v[l] = (const float*)d_in[k];
            else if (sz == NG * 3 * M * 32) p.g[l] = (const float*)d_in[k];
        }
    }
    float* out = (float*)d_out;

    values_kernel<<<NS, 192>>>(p, out);
    grads_kernel<<<dim3(3, NG), 192>>>(p, gidx, out + (size_t)NS * NSOAP);
    (void)out_size;
}

// round 2
// speedup vs baseline: 1.1168x; 1.1168x over previous
#include <cuda_runtime.h>
#include <cstddef>

#define NS 2000
#define NG 10000
#define NSOAP 6144

struct Ptrs { const float* v[6]; const float* g[6]; };

__constant__ float FAC[6] = {
    1.0f,
    0.5773502691896258f,   // 1/sqrt(3)
    0.4472135954999579f,   // 1/sqrt(5)
    0.3779644730092272f,   // 1/sqrt(7)
    0.3333333333333333f,   // 1/sqrt(9)
    0.30151134457776363f   // 1/sqrt(11)
};

// smem offset for l-block: sum_{l'<l} (2l'+1)*32 = 32*l*l
__device__ __forceinline__ int loff(int l) { return 32 * l * l; }

typedef unsigned long long u64;

__device__ __forceinline__ u64 fma2(u64 a, u64 b, u64 c) {
    u64 d;
    asm("fma.rn.f32x2 %0, %1, %2, %3;" : "=l"(d) : "l"(a), "l"(b), "l"(c));
    return d;
}
__device__ __forceinline__ u64 dup2(float x) {
    u64 d;
    asm("mov.b64 %0, {%1, %1};" : "=l"(d) : "f"(x));
    return d;
}
union U64F2 { u64 u; float2 f; };

// ---------------------------------------------------------------------------
// values: out[i, l_block, a, b] = fac_l * sum_m v[i,m,a] * v[i,m,b]
// 1 block per i; 6 warps, warp w handles l=w; lane computes 8x4 tile.
// ---------------------------------------------------------------------------
__global__ void __launch_bounds__(192) values_kernel(Ptrs p, float* __restrict__ out) {
    __shared__ __align__(16) float sv[1152];
    const int i = blockIdx.x;
    const int tid = threadIdx.x;

#pragma unroll
    for (int l = 0; l < 6; ++l) {
        const int cnt4 = (2 * l + 1) * 8;
        const float4* src = (const float4*)(p.v[l] + (size_t)i * (2 * l + 1) * 32);
        float4* dst = (float4*)(sv + loff(l));
        for (int j = tid; j < cnt4; j += 192) dst[j] = src[j];
    }
    __syncthreads();

    const int l = tid >> 5;
    const int lane = tid & 31;
    const int a0 = (lane >> 3) * 8;
    const int b0 = (lane & 7) * 4;
    const float* base = sv + loff(l);
    const int M = 2 * l + 1;

    float acc[8][4];
#pragma unroll
    for (int r = 0; r < 8; ++r)
#pragma unroll
        for (int c = 0; c < 4; ++c) acc[r][c] = 0.0f;

    for (int m = 0; m < M; ++m) {
        const float* row = base + m * 32;
        float4 a0v = *(const float4*)(row + a0);
        float4 a1v = *(const float4*)(row + a0 + 4);
        float4 bv  = *(const float4*)(row + b0);
        float av[8] = {a0v.x, a0v.y, a0v.z, a0v.w, a1v.x, a1v.y, a1v.z, a1v.w};
        float bb[4] = {bv.x, bv.y, bv.z, bv.w};
#pragma unroll
        for (int r = 0; r < 8; ++r)
#pragma unroll
            for (int c = 0; c < 4; ++c) acc[r][c] += av[r] * bb[c];
    }

    const float fac = FAC[l];
    float* o = out + (size_t)i * NSOAP + l * 1024 + a0 * 32 + b0;
#pragma unroll
    for (int r = 0; r < 8; ++r) {
        float4 s = make_float4(fac * acc[r][0], fac * acc[r][1],
                               fac * acc[r][2], fac * acc[r][3]);
        __stcs((float4*)(o + r * 32), s);
    }
}

// ---------------------------------------------------------------------------
// grads tile compute: T[a,b] = sum_m ( g[m,a]*vg[m,b] + vg[m,a]*g[m,b] )
// lane computes 8 rows x 4 cols; rows packed in pairs into f32x2 accumulators.
// ---------------------------------------------------------------------------
__device__ __forceinline__ void grads_tile(const float* __restrict__ gb,
                                           const float* __restrict__ vb,
                                           int M, int a0, int b0,
                                           float* __restrict__ o) {
    u64 acc[4][4];
#pragma unroll
    for (int r = 0; r < 4; ++r)
#pragma unroll
        for (int c = 0; c < 4; ++c) acc[r][c] = 0ull;

    for (int m = 0; m < M; ++m) {
        const float* rg = gb + m * 32;
        const float* rv = vb + m * 32;
        // row-pair operands (8 floats = 4 x f32x2), 32B-aligned LDS.64 loads
        u64 ga2[4], va2[4];
#pragma unroll
        for (int r = 0; r < 4; ++r) {
            ga2[r] = *(const u64*)(rg + a0 + 2 * r);
            va2[r] = *(const u64*)(rv + a0 + 2 * r);
        }
        float4 gc4 = *(const float4*)(rg + b0);
        float4 vc4 = *(const float4*)(rv + b0);
        u64 gd[4] = {dup2(gc4.x), dup2(gc4.y), dup2(gc4.z), dup2(gc4.w)};
        u64 vd[4] = {dup2(vc4.x), dup2(vc4.y), dup2(vc4.z), dup2(vc4.w)};
#pragma unroll
        for (int r = 0; r < 4; ++r)
#pragma unroll
            for (int c = 0; c < 4; ++c) {
                acc[r][c] = fma2(ga2[r], vd[c], acc[r][c]);
                acc[r][c] = fma2(va2[r], gd[c], acc[r][c]);
            }
    }

    // unpack: acc[r][c] holds rows (a0+2r, a0+2r+1) at column b0+c
#pragma unroll
    for (int r = 0; r < 4; ++r) {
        U64F2 u0, u1, u2, u3;
        u0.u = acc[r][0]; u1.u = acc[r][1]; u2.u = acc[r][2]; u3.u = acc[r][3];
        float4 lo = make_float4(u0.f.x, u1.f.x, u2.f.x, u3.f.x);
        float4 hi = make_float4(u0.f.y, u1.f.y, u2.f.y, u3.f.y);
        float* orow = o + (a0 + 2 * r) * 32 + b0;
        __stcs((float4*)orow, lo);
        __stcs((float4*)(orow + 32), hi);
    }
}

// ---------------------------------------------------------------------------
// grads: one block handles TWO (i,x) pairs (e0 = 2*blk, e1 = e0+1).
// 6 warps; warp w: pair pi = w/3, k = w%3, handles l = 5-k then l = k
// -> every warp does exactly 12 m-steps (perfect balance).
// ---------------------------------------------------------------------------
__global__ void __launch_bounds__(192, 5) grads_kernel(Ptrs p,
                                                       const int* __restrict__ gidx,
                                                       float* __restrict__ out) {
    __shared__ __align__(16) float sg[2][1152];
    __shared__ __align__(16) float svg[2][1152];
    const int e0 = 2 * blockIdx.x;
    const int tid = threadIdx.x;

#pragma unroll
    for (int pi = 0; pi < 2; ++pi) {
        const int e = e0 + pi;
        const int s = gidx[e / 3];
#pragma unroll
        for (int l = 0; l < 6; ++l) {
            const int cnt4 = (2 * l + 1) * 8;
            const float4* gs = (const float4*)(p.g[l] + (size_t)e * (2 * l + 1) * 32);
            const float4* vs = (const float4*)(p.v[l] + (size_t)s * (2 * l + 1) * 32);
            const float fac = FAC[l];
            float4* dg = (float4*)(sg[pi] + loff(l));
            float4* dv = (float4*)(svg[pi] + loff(l));
            for (int j = tid; j < cnt4; j += 192) {
                dg[j] = __ldcs(gs + j);            // read-once: stream past L2
                float4 t = vs[j];                  // reused across blocks: keep in L2
                dv[j] = make_float4(fac * t.x, fac * t.y, fac * t.z, fac * t.w);
            }
        }
    }
    __syncthreads();

    const int w = tid >> 5;
    const int lane = tid & 31;
    const int pi = w / 3;
    const int k = w % 3;
    const int a0 = (lane >> 3) * 8;
    const int b0 = (lane & 7) * 4;
    const int e = e0 + pi;
    float* obase = out + (size_t)e * NSOAP;

    // first l-task: l = 5-k (M = 11-2k), then l = k (M = 2k+1)
    {
        const int l = 5 - k;
        grads_tile(sg[pi] + loff(l), svg[pi] + loff(l), 2 * l + 1, a0, b0,
                   obase + l * 1024);
    }
    {
        const int l = k;
        grads_tile(sg[pi] + loff(l), svg[pi] + loff(l), 2 * l + 1, a0, b0,
                   obase + l * 1024);
    }
}

// ---------------------------------------------------------------------------
extern "C" void kernel_launch(void* const* d_in, const int* in_sizes, int n_in,
                              void* d_out, int out_size) {
    Ptrs p;
    const int* gidx = nullptr;
    for (int k = 0; k < n_in; ++k) {
        const int sz = in_sizes[k];
        if (sz == NG) { gidx = (const int*)d_in[k]; continue; }
        for (int l = 0; l < 6; ++l) {
            const int M = 2 * l + 1;
            if (sz == NS * M * 32)          p.v[l] = (const float*)d_in[k];
            else if (sz == NG * 3 * M * 32) p.g[l] = (const float*)d_in[k];
        }
    }
    float* out = (float*)d_out;

    values_kernel<<<NS, 192>>>(p, out);
    grads_kernel<<<NG * 3 / 2, 192>>>(p, gidx, out + (size_t)NS * NSOAP);
    (void)out_size;
}